// round 4
// baseline (speedup 1.0000x reference)
#include <cuda_runtime.h>

typedef unsigned long long u64;
typedef unsigned int u32;

#define EPSV   1e-3f
#define ALPHAV 0.3f

#define Bn  16
#define Hn  64
#define Wn  64
#define Cn  1024
#define Gn  32
#define CGn 32
#define HT  8
#define WT  32
#define NPOS (HT * WT)            // 256 positions per tile

#define DY_STRIDE 9               // padded stride (float4 units)
#define DY_F4  (NPOS * DY_STRIDE) // 2304
#define PW_F4  256
#define SMEM_BYTES ((DY_F4 + PW_F4) * 16 + 64 * 4)  // ~41.2 KB

__device__ __forceinline__ u64 ffma2(u64 a, u64 b, u64 c) {
    u64 d;
    asm("fma.rn.f32x2 %0, %1, %2, %3;" : "=l"(d) : "l"(a), "l"(b), "l"(c));
    return d;
}
__device__ __forceinline__ u64 pack2(float x, float y) {
    u64 d;
    asm("mov.b64 %0, {%1, %2};" : "=l"(d) : "f"(x), "f"(y));
    return d;
}
__device__ __forceinline__ float2 unpack2(u64 a) {
    float2 r;
    asm("mov.b64 {%0, %1}, %2;" : "=f"(r.x), "=f"(r.y) : "l"(a));
    return r;
}
__device__ __forceinline__ void cp16(u32 dst, const void* src) {
    asm volatile("cp.async.cg.shared.global [%0], [%1], 16;"
                 :: "r"(dst), "l"(src));
}

__global__ __launch_bounds__(512, 2)
void fused_gconv_kernel(const float* __restrict__ x,
                        const float* __restrict__ dwk,
                        const float* __restrict__ pwk,
                        const float* __restrict__ gamma,
                        const float* __restrict__ beta,
                        const float* __restrict__ mmean,
                        const float* __restrict__ mvar,
                        float* __restrict__ out)
{
    extern __shared__ float4 sm4[];
    float4* dy4 = sm4;                      // [256 pos][9] float4 (8 used + 1 pad)
    float4* pw4 = dy4 + DY_F4;              // [32 c][8 d4] float4
    float*  sbs = (float*)(pw4 + PW_F4);    // 32 floats scale
    float*  sbb = sbs + 32;                 // 32 floats bias

    const int g  = blockIdx.x;
    const int ht = blockIdx.y >> 1;
    const int wt = blockIdx.y & 1;
    const int b  = blockIdx.z;
    const int h0 = ht * HT;
    const int w0 = wt * WT;
    const int t  = threadIdx.x;
    const int c0 = g * CGn;

    // ---- async load: pointwise weights for this group (1024 floats) ----
    if (t < 256) {
        const u32 pw_s = (u32)__cvta_generic_to_shared(pw4);
        cp16(pw_s + t * 16, pwk + g * CGn * CGn + t * 4);
    }
    asm volatile("cp.async.commit_group;");

    // ---- BN scale/bias ----
    if (t < 32) {
        const int c = c0 + t;
        const float s = gamma[c] * rsqrtf(mvar[c] + EPSV);
        sbs[t] = s;
        sbb[t] = beta[c] - mmean[c] * s;
    }

    // ---- depthwise 3x3 straight from global (L1D is the stage) ----
    // thread -> (c4 = t&7, wl = (t>>3)&31, rb = t>>8): 4 rows x 1 col x 4 ch
    {
        const int c4 = t & 7;
        const int wl = (t >> 3) & 31;
        const int rb = t >> 8;           // 0 or 1
        const float* xb = x + (u64)b * Hn * Wn * Cn + c0 + c4 * 4;
        const int wbase = w0 - 1 + wl;
        const int hbase = h0 + rb * 4 - 1;

        u64 a0[4], a1[4];
        #pragma unroll
        for (int o = 0; o < 4; o++) { a0[o] = 0ull; a1[o] = 0ull; }

        #pragma unroll
        for (int kw = 0; kw < 3; kw++) {
            u64 ka[3], kb[3];
            #pragma unroll
            for (int kr = 0; kr < 3; kr++) {
                const ulonglong2 kv =
                    *(const ulonglong2*)(dwk + (kr * 3 + kw) * Cn + c0 + c4 * 4);
                ka[kr] = kv.x; kb[kr] = kv.y;
            }
            const int w = wbase + kw;
            const bool wok = (unsigned)w < (unsigned)Wn;
            #pragma unroll
            for (int rr = 0; rr < 6; rr++) {
                const int h = hbase + rr;
                ulonglong2 v; v.x = 0ull; v.y = 0ull;
                if (wok && (unsigned)h < (unsigned)Hn)
                    v = *(const ulonglong2*)(xb + ((u64)h * Wn + w) * Cn);
                #pragma unroll
                for (int kr = 0; kr < 3; kr++) {
                    const int o = rr - kr;
                    if (o >= 0 && o < 4) {
                        a0[o] = ffma2(v.x, ka[kr], a0[o]);
                        a1[o] = ffma2(v.y, kb[kr], a1[o]);
                    }
                }
            }
        }
        #pragma unroll
        for (int o = 0; o < 4; o++) {
            ulonglong2 st; st.x = a0[o]; st.y = a1[o];
            *(ulonglong2*)&dy4[((rb * 4 + o) * 32 + wl) * DY_STRIDE + c4] = st;
        }
    }

    asm volatile("cp.async.wait_group 0;" ::: "memory");
    __syncthreads();

    // ---- pointwise 32x32 per group + BN + LeakyReLU ----
    // thread -> (dgroup = t&7: 4 output channels, posset = t>>3: 4 positions)
    const int dgroup = t & 7;
    const int d0 = dgroup * 4;
    const int posset = t >> 3;       // 0..63; positions posset + 64*i

    u64 acc[4][2];
    #pragma unroll
    for (int i = 0; i < 4; i++) { acc[i][0] = 0ull; acc[i][1] = 0ull; }

    #pragma unroll
    for (int cq = 0; cq < 8; cq++) {
        float4 dyv[4];
        #pragma unroll
        for (int i = 0; i < 4; i++)
            dyv[i] = dy4[(posset + 64 * i) * DY_STRIDE + cq];
        #pragma unroll
        for (int cc = 0; cc < 4; cc++) {
            const int c = cq * 4 + cc;
            const ulonglong2 pa = *(const ulonglong2*)&pw4[c * 8 + dgroup];
            #pragma unroll
            for (int i = 0; i < 4; i++) {
                const float dc = ((const float*)&dyv[i])[cc];
                const u64 dp = pack2(dc, dc);
                acc[i][0] = ffma2(dp, pa.x, acc[i][0]);
                acc[i][1] = ffma2(dp, pa.y, acc[i][1]);
            }
        }
    }

    // epilogue: BN (one FFMA2 per pair) + LeakyReLU + full-line stores
    const ulonglong2 S  = *(const ulonglong2*)&sbs[d0];
    const ulonglong2 Bb = *(const ulonglong2*)&sbb[d0];
    #pragma unroll
    for (int i = 0; i < 4; i++) {
        const int p = posset + 64 * i;
        const int row = p >> 5, wloc = p & 31;
        const u64 y0 = ffma2(acc[i][0], S.x, Bb.x);
        const u64 y1 = ffma2(acc[i][1], S.y, Bb.y);
        const float2 f0 = unpack2(y0), f1 = unpack2(y1);
        float r[4] = {f0.x, f0.y, f1.x, f1.y};
        #pragma unroll
        for (int k = 0; k < 4; k++)
            r[k] = fmaxf(r[k], 0.f) + ALPHAV * fminf(r[k], 0.f);
        float* op = out + (((u64)b * Hn + h0 + row) * Wn + w0 + wloc) * Cn + c0 + d0;
        *(float4*)op = make_float4(r[0], r[1], r[2], r[3]);
    }
}

extern "C" void kernel_launch(void* const* d_in, const int* in_sizes, int n_in,
                              void* d_out, int out_size)
{
    const float* x     = (const float*)d_in[0];
    const float* dwk   = (const float*)d_in[1];
    const float* pwk   = (const float*)d_in[2];
    const float* gam   = (const float*)d_in[3];
    const float* bet   = (const float*)d_in[4];
    const float* mmean = (const float*)d_in[5];
    const float* mvar  = (const float*)d_in[6];
    float* out = (float*)d_out;

    cudaFuncSetAttribute(fused_gconv_kernel,
                         cudaFuncAttributeMaxDynamicSharedMemorySize, SMEM_BYTES);

    dim3 grid(Gn, (Hn / HT) * (Wn / WT), Bn);   // 32 x 16 x 16 = 8192 blocks
    fused_gconv_kernel<<<grid, 512, SMEM_BYTES>>>(x, dwk, pwk, gam, bet, mmean, mvar, out);
}

// round 5
// speedup vs baseline: 1.2571x; 1.2571x over previous
#include <cuda_runtime.h>

typedef unsigned long long u64;
typedef unsigned int u32;

#define EPSV   1e-3f
#define ALPHAV 0.3f

#define Bn  16
#define Hn  64
#define Wn  64
#define Cn  1024
#define Gn  32
#define CGn 32
#define HT  8
#define WT  32
#define NPOS (HT * WT)            // 256 positions per tile

#define DY_STRIDE 9               // padded stride (float4 units)
#define DY_F4  (NPOS * DY_STRIDE) // 2304
#define PW_F4  256
#define SMEM_BYTES ((DY_F4 + PW_F4) * 16 + 64 * 4)  // ~41.2 KB

__device__ __forceinline__ u64 ffma2(u64 a, u64 b, u64 c) {
    u64 d;
    asm("fma.rn.f32x2 %0, %1, %2, %3;" : "=l"(d) : "l"(a), "l"(b), "l"(c));
    return d;
}
__device__ __forceinline__ u64 pack2(float x, float y) {
    u64 d;
    asm("mov.b64 %0, {%1, %2};" : "=l"(d) : "f"(x), "f"(y));
    return d;
}
__device__ __forceinline__ float2 unpack2(u64 a) {
    float2 r;
    asm("mov.b64 {%0, %1}, %2;" : "=f"(r.x), "=f"(r.y) : "l"(a));
    return r;
}
__device__ __forceinline__ void cp16(u32 dst, const void* src) {
    asm volatile("cp.async.cg.shared.global [%0], [%1], 16;"
                 :: "r"(dst), "l"(src));
}

__global__ __launch_bounds__(256, 3)
void fused_gconv_kernel(const float* __restrict__ x,
                        const float* __restrict__ dwk,
                        const float* __restrict__ pwk,
                        const float* __restrict__ gamma,
                        const float* __restrict__ beta,
                        const float* __restrict__ mmean,
                        const float* __restrict__ mvar,
                        float* __restrict__ out)
{
    extern __shared__ float4 sm4[];
    float4* dy4 = sm4;                      // [256 pos][9] float4 (8 used + 1 pad)
    float4* pw4 = dy4 + DY_F4;              // [32 c][8 d4] float4
    float*  sbs = (float*)(pw4 + PW_F4);    // 32 floats scale
    float*  sbb = sbs + 32;                 // 32 floats bias

    const int g  = blockIdx.x;
    const int ht = blockIdx.y >> 1;
    const int wt = blockIdx.y & 1;
    const int b  = blockIdx.z;
    const int h0 = ht * HT;
    const int w0 = wt * WT;
    const int t  = threadIdx.x;
    const int c0 = g * CGn;

    // ---- async load: pointwise weights for this group (1024 floats) ----
    {
        const u32 pw_s = (u32)__cvta_generic_to_shared(pw4);
        cp16(pw_s + t * 16, pwk + g * CGn * CGn + t * 4);
        asm volatile("cp.async.commit_group;");
    }

    // ---- BN scale/bias ----
    if (t < 32) {
        const int c = c0 + t;
        const float s = gamma[c] * rsqrtf(mvar[c] + EPSV);
        sbs[t] = s;
        sbb[t] = beta[c] - mmean[c] * s;
    }

    // ---- depthwise 3x3 straight from global (L1D is the stage) ----
    // thread -> 4 rows x 4 cols x 2 channels (c2 = t&15, wq = (t>>4)&7, rb = t>>7)
    {
        const int c2 = t & 15;
        const int wq = (t >> 4) & 7;
        const int rb = t >> 7;           // 0 or 1
        const float* xb = x + (u64)b * Hn * Wn * Cn + c0 + c2 * 2;
        const int wbase = w0 + wq * 4 - 1;
        const int hbase = h0 + rb * 4 - 1;

        // 9 depthwise taps for this channel pair
        u64 kreg[9];
        #pragma unroll
        for (int tap = 0; tap < 9; tap++)
            kreg[tap] = *(const u64*)(dwk + tap * Cn + c0 + c2 * 2);

        u64 acc[4][4];   // [orow][ocol]
        #pragma unroll
        for (int i = 0; i < 4; i++)
            #pragma unroll
            for (int j = 0; j < 4; j++) acc[i][j] = 0ull;

        #pragma unroll
        for (int ci = 0; ci < 6; ci++) {
            const int w = wbase + ci;
            const bool wok = (unsigned)w < (unsigned)Wn;
            u64 col[6];
            #pragma unroll
            for (int rr = 0; rr < 6; rr++) {
                const int h = hbase + rr;
                col[rr] = (wok && (unsigned)h < (unsigned)Hn)
                          ? *(const u64*)(xb + ((u64)h * Wn + w) * Cn) : 0ull;
            }
            #pragma unroll
            for (int kw = 0; kw < 3; kw++) {
                const int oc = ci - kw;
                if (oc >= 0 && oc < 4) {
                    #pragma unroll
                    for (int kr = 0; kr < 3; kr++) {
                        #pragma unroll
                        for (int orow = 0; orow < 4; orow++) {
                            acc[orow][oc] =
                                ffma2(col[orow + kr], kreg[kr * 3 + kw], acc[orow][oc]);
                        }
                    }
                }
            }
        }

        // write dy: 16 x 8B stores, conflict-free (c2 lanes contiguous 128B)
        char* dyb = (char*)dy4;
        #pragma unroll
        for (int orow = 0; orow < 4; orow++) {
            #pragma unroll
            for (int oc = 0; oc < 4; oc++) {
                const int pos = (rb * 4 + orow) * 32 + wq * 4 + oc;
                *(u64*)(dyb + pos * (DY_STRIDE * 16) + c2 * 8) = acc[orow][oc];
            }
        }
    }

    asm volatile("cp.async.wait_group 0;" ::: "memory");
    __syncthreads();

    // ---- pointwise 32x32 per group + BN + LeakyReLU (4 pos x 8 d / thread) ----
    const int dgroup = t & 3;        // which 8 output channels
    const int d0 = dgroup * 8;
    const int posset = t >> 2;       // 0..63; positions posset + 64*i

    u64 acc[4][4];
    #pragma unroll
    for (int i = 0; i < 4; i++)
        #pragma unroll
        for (int j = 0; j < 4; j++) acc[i][j] = 0ull;

    #pragma unroll
    for (int cq = 0; cq < 8; cq++) {
        float4 dyv[4];
        #pragma unroll
        for (int i = 0; i < 4; i++)
            dyv[i] = dy4[(posset + 64 * i) * DY_STRIDE + cq];
        #pragma unroll
        for (int cc = 0; cc < 4; cc++) {
            const int c = cq * 4 + cc;
            const ulonglong2 pa = *(const ulonglong2*)&pw4[c * 8 + dgroup * 2];
            const ulonglong2 pb = *(const ulonglong2*)&pw4[c * 8 + dgroup * 2 + 1];
            #pragma unroll
            for (int i = 0; i < 4; i++) {
                const float dc = ((const float*)&dyv[i])[cc];
                const u64 dp = pack2(dc, dc);
                acc[i][0] = ffma2(dp, pa.x, acc[i][0]);
                acc[i][1] = ffma2(dp, pa.y, acc[i][1]);
                acc[i][2] = ffma2(dp, pb.x, acc[i][2]);
                acc[i][3] = ffma2(dp, pb.y, acc[i][3]);
            }
        }
    }

    // epilogue: BN (one FFMA2 per pair) + LeakyReLU + store
    const ulonglong2 S0  = *(const ulonglong2*)&sbs[d0];
    const ulonglong2 S1  = *(const ulonglong2*)&sbs[d0 + 4];
    const ulonglong2 Bb0 = *(const ulonglong2*)&sbb[d0];
    const ulonglong2 Bb1 = *(const ulonglong2*)&sbb[d0 + 4];
    #pragma unroll
    for (int i = 0; i < 4; i++) {
        const int p = posset + 64 * i;
        const int row = p >> 5, wloc = p & 31;
        const u64 y0 = ffma2(acc[i][0], S0.x, Bb0.x);
        const u64 y1 = ffma2(acc[i][1], S0.y, Bb0.y);
        const u64 y2 = ffma2(acc[i][2], S1.x, Bb1.x);
        const u64 y3 = ffma2(acc[i][3], S1.y, Bb1.y);
        const float2 f0 = unpack2(y0), f1 = unpack2(y1);
        const float2 f2 = unpack2(y2), f3 = unpack2(y3);
        float r[8] = {f0.x, f0.y, f1.x, f1.y, f2.x, f2.y, f3.x, f3.y};
        #pragma unroll
        for (int k = 0; k < 8; k++)
            r[k] = fmaxf(r[k], 0.f) + ALPHAV * fminf(r[k], 0.f);
        float* op = out + (((u64)b * Hn + h0 + row) * Wn + w0 + wloc) * Cn + c0 + d0;
        *(float4*)op       = make_float4(r[0], r[1], r[2], r[3]);
        *(float4*)(op + 4) = make_float4(r[4], r[5], r[6], r[7]);
    }
}

extern "C" void kernel_launch(void* const* d_in, const int* in_sizes, int n_in,
                              void* d_out, int out_size)
{
    const float* x     = (const float*)d_in[0];
    const float* dwk   = (const float*)d_in[1];
    const float* pwk   = (const float*)d_in[2];
    const float* gam   = (const float*)d_in[3];
    const float* bet   = (const float*)d_in[4];
    const float* mmean = (const float*)d_in[5];
    const float* mvar  = (const float*)d_in[6];
    float* out = (float*)d_out;

    cudaFuncSetAttribute(fused_gconv_kernel,
                         cudaFuncAttributeMaxDynamicSharedMemorySize, SMEM_BYTES);

    dim3 grid(Gn, (Hn / HT) * (Wn / WT), Bn);   // 32 x 16 x 16 = 8192 blocks
    fused_gconv_kernel<<<grid, 256, SMEM_BYTES>>>(x, dwk, pwk, gam, bet, mmean, mvar, out);
}